// round 6
// baseline (speedup 1.0000x reference)
#include <cuda_runtime.h>
#include <cuda_bf16.h>

// Problem constants (fixed by the dataset)
#define BB      4
#define CC      8
#define NVOX    1048576      // 64*128*128
#define K_RATIO 0.2f

// Linear histogram: idx = min((int)(ce * 256.f), NB-1), range [0, 16)
#define NB      4096
#define BSCALE  256.0f

#define GRID1B  296          // blocks per batch for pass1 (1184 total)
#define THR1    256
#define BLK3    74           // blocks per batch for pass3 (296 total)
#define THR3    512

// ---- static device scratch (no allocations allowed) ----
__device__ unsigned int g_hist[BB][NB];
__device__ float        g_scratch[(size_t)BB * NVOX];   // 16 MB
__device__ int          g_T[BB];
__device__ int          g_k[BB];
__device__ int          g_nvalid[BB];
__device__ long long    g_above[BB];
__device__ double       g_pa[BB][BLK3];
__device__ double       g_pb[BB][BLK3];

// ---------------------------------------------------------------------------
// Kernel 0: zero the global histogram (replayed every graph launch)
// ---------------------------------------------------------------------------
__global__ void k_zero() {
    int total = BB * NB;
    for (int i = blockIdx.x * blockDim.x + threadIdx.x; i < total;
         i += gridDim.x * blockDim.x)
        ((unsigned int*)g_hist)[i] = 0u;
}

// ---------------------------------------------------------------------------
// Pass 1: compute CE per voxel, write CE scratch, RED counts straight to L2
// ---------------------------------------------------------------------------
__device__ __forceinline__ float vox_ce(float a0, float a1, float a2, float a3,
                                        float a4, float a5, float a6, float a7,
                                        int t, unsigned int* hist) {
    float m = fmaxf(fmaxf(fmaxf(a0, a1), fmaxf(a2, a3)),
                    fmaxf(fmaxf(a4, a5), fmaxf(a6, a7)));
    float s = __expf(a0 - m) + __expf(a1 - m) + __expf(a2 - m) + __expf(a3 - m)
            + __expf(a4 - m) + __expf(a5 - m) + __expf(a6 - m) + __expf(a7 - m);
    float xt = a0;
    if (t == 1) xt = a1;
    if (t == 2) xt = a2;
    if (t == 3) xt = a3;
    if (t == 4) xt = a4;
    if (t == 5) xt = a5;
    if (t == 6) xt = a6;
    if (t == 7) xt = a7;
    float ce = fmaxf(m + __logf(s) - xt, 0.0f);
    if (t != 0) {
        int idx = (int)(ce * BSCALE);
        if (idx > NB - 1) idx = NB - 1;
        atomicAdd(&hist[idx], 1u);   // return unused -> REDG, no shared floor
        return ce;
    }
    return -1.0f;
}

__global__ void __launch_bounds__(THR1, 4)
k_pass1(const float* __restrict__ logits, const int* __restrict__ target) {
    const int tid = threadIdx.x;
    const int b = blockIdx.y;
    const float* Lp = logits + (size_t)b * CC * NVOX;
    const int* Tp = target + (size_t)b * NVOX;
    float* Sp = g_scratch + (size_t)b * NVOX;
    unsigned int* hist = g_hist[b];

    const int stride = GRID1B * THR1 * 4;
    for (int i0 = (blockIdx.x * THR1 + tid) * 4; i0 < NVOX; i0 += stride) {
        float4 x0 = *(const float4*)(Lp + 0 * NVOX + i0);
        float4 x1 = *(const float4*)(Lp + 1 * NVOX + i0);
        float4 x2 = *(const float4*)(Lp + 2 * NVOX + i0);
        float4 x3 = *(const float4*)(Lp + 3 * NVOX + i0);
        float4 x4 = *(const float4*)(Lp + 4 * NVOX + i0);
        float4 x5 = *(const float4*)(Lp + 5 * NVOX + i0);
        float4 x6 = *(const float4*)(Lp + 6 * NVOX + i0);
        float4 x7 = *(const float4*)(Lp + 7 * NVOX + i0);
        int4 t4 = *(const int4*)(Tp + i0);   // int32 targets: 4 voxels per load

        float4 outv;
        outv.x = vox_ce(x0.x, x1.x, x2.x, x3.x, x4.x, x5.x, x6.x, x7.x, t4.x, hist);
        outv.y = vox_ce(x0.y, x1.y, x2.y, x3.y, x4.y, x5.y, x6.y, x7.y, t4.y, hist);
        outv.z = vox_ce(x0.z, x1.z, x2.z, x3.z, x4.z, x5.z, x6.z, x7.z, t4.z, hist);
        outv.w = vox_ce(x0.w, x1.w, x2.w, x3.w, x4.w, x5.w, x6.w, x7.w, t4.w, hist);
        *(float4*)(Sp + i0) = outv;
    }
}

// ---------------------------------------------------------------------------
// Pass 2: per batch (one block each), find n_valid, k, boundary bucket T
// ---------------------------------------------------------------------------
#define CH (NB / 1024)   // 4 buckets per thread

__global__ void k_pass2() {
    __shared__ unsigned int part[1024];
    __shared__ unsigned int warpsum[32];
    const int tid = threadIdx.x;
    const int b = blockIdx.x;

    unsigned int s = 0;
    const int base = tid * CH;
#pragma unroll
    for (int j = 0; j < CH; j++) s += g_hist[b][base + j];
    part[tid] = s;
    __syncthreads();

    if (tid < 32) {
        unsigned int w = 0;
#pragma unroll
        for (int j = 0; j < 32; j++) w += part[tid * 32 + j];
        warpsum[tid] = w;
    }
    __syncthreads();

    if (tid == 0) {
        long long nv = 0;
        for (int j = 0; j < 32; j++) nv += warpsum[j];
        int n_valid = (int)nv;
        // replicate reference: trunc(f32(n_valid) * f32(0.2)), clamp [1, n_valid]
        int k = (int)((float)n_valid * K_RATIO);
        if (k < 1) k = 1;
        if (k > n_valid) k = n_valid;   // == 0 iff n_valid == 0
        g_k[b] = k;
        g_nvalid[b] = n_valid;

        if (k > 0) {
            long long cum = 0;
            int wsel = 0;
            for (int wi = 31; wi >= 0; wi--) {
                if (cum + (long long)warpsum[wi] >= (long long)k) { wsel = wi; break; }
                cum += warpsum[wi];
            }
            int psel = wsel * 32;
            for (int pi = wsel * 32 + 31; pi >= wsel * 32; pi--) {
                if (cum + (long long)part[pi] >= (long long)k) { psel = pi; break; }
                cum += part[pi];
            }
            int T = psel * CH;
            for (int j = psel * CH + CH - 1; j >= psel * CH; j--) {
                unsigned int c = g_hist[b][j];
                if (cum + (long long)c >= (long long)k) { T = j; break; }
                cum += c;
            }
            g_T[b] = T;
            g_above[b] = cum;   // count strictly above bucket T
        } else {
            g_T[b] = 0;         // sentinel; nv==0 path ignores it
            g_above[b] = 0;
        }
    }
}

// ---------------------------------------------------------------------------
// Pass 3: exact sums — values in buckets > T, and values in bucket T
// 16 floats per thread per iteration for MLP.
// ---------------------------------------------------------------------------
__global__ void __launch_bounds__(THR3)
k_pass3() {
    const int b = blockIdx.y;
    const int T = g_T[b];
    const float* Sp = g_scratch + (size_t)b * NVOX;

    float sa = 0.0f, sb = 0.0f;
    const int stride = BLK3 * THR3 * 16;
    for (int i0 = (blockIdx.x * THR3 + threadIdx.x) * 16; i0 < NVOX; i0 += stride) {
        float4 v0 = *(const float4*)(Sp + i0);
        float4 v1 = *(const float4*)(Sp + i0 + 4);
        float4 v2 = *(const float4*)(Sp + i0 + 8);
        float4 v3 = *(const float4*)(Sp + i0 + 12);
#define ACC(F) { float f = (F); if (f >= 0.0f) { \
            int idx = (int)(f * BSCALE); if (idx > NB - 1) idx = NB - 1; \
            if (idx > T) sa += f; else if (idx == T) sb += f; } }
        ACC(v0.x) ACC(v0.y) ACC(v0.z) ACC(v0.w)
        ACC(v1.x) ACC(v1.y) ACC(v1.z) ACC(v1.w)
        ACC(v2.x) ACC(v2.y) ACC(v2.z) ACC(v2.w)
        ACC(v3.x) ACC(v3.y) ACC(v3.z) ACC(v3.w)
#undef ACC
    }

    // deterministic block reduction in double
    double da = sa, db = sb;
#pragma unroll
    for (int o = 16; o > 0; o >>= 1) {
        da += __shfl_down_sync(0xFFFFFFFFu, da, o);
        db += __shfl_down_sync(0xFFFFFFFFu, db, o);
    }
    __shared__ double ra[16], rb[16];
    const int wid = threadIdx.x >> 5, lane = threadIdx.x & 31;
    if (lane == 0) { ra[wid] = da; rb[wid] = db; }
    __syncthreads();
    if (wid == 0) {
        da = (lane < (THR3 / 32)) ? ra[lane] : 0.0;
        db = (lane < (THR3 / 32)) ? rb[lane] : 0.0;
#pragma unroll
        for (int o = 8; o > 0; o >>= 1) {
            da += __shfl_down_sync(0xFFFFFFFFu, da, o);
            db += __shfl_down_sync(0xFFFFFFFFu, db, o);
        }
        if (lane == 0) {
            g_pa[b][blockIdx.x] = da;
            g_pb[b][blockIdx.x] = db;
        }
    }
}

// ---------------------------------------------------------------------------
// Pass 4: combine — one warp per batch (74 partials each), then scalar mean
// ---------------------------------------------------------------------------
__global__ void k_pass4(float* __restrict__ out) {
    const int tid = threadIdx.x;
    const int w = tid >> 5, lane = tid & 31;
    __shared__ double per[BB];
    if (w < BB) {
        const int b = w;
        double da = 0.0, db = 0.0;
        for (int i = lane; i < BLK3; i += 32) {
            da += g_pa[b][i];
            db += g_pb[b][i];
        }
#pragma unroll
        for (int o = 16; o > 0; o >>= 1) {
            da += __shfl_down_sync(0xFFFFFFFFu, da, o);
            db += __shfl_down_sync(0xFFFFFFFFu, db, o);
        }
        if (lane == 0) {
            const int nv = g_nvalid[b];
            const int k = g_k[b];
            double p;
            if (nv == 0) {
                p = 0.0;   // fallback: mean of all-zero CE
            } else {
                const int T = g_T[b];
                const long long above = g_above[b];
                const long long r = (long long)k - above;   // 1..cnt[T]
                const unsigned int cnt = g_hist[b][T];
                const double mean_bb = cnt ? (db / (double)cnt) : 0.0;
                const double top_sum = da + (double)r * mean_bb;
                p = top_sum / (double)k;
            }
            per[b] = p;
        }
    }
    __syncthreads();
    if (tid == 0) {
        double acc = 0.0;
        for (int b = 0; b < BB; b++) acc += per[b];
        out[0] = (float)(acc / (double)BB);
    }
}

// ---------------------------------------------------------------------------
// Launch
// ---------------------------------------------------------------------------
extern "C" void kernel_launch(void* const* d_in, const int* in_sizes, int n_in,
                              void* d_out, int out_size) {
    const float* logits = (const float*)d_in[0];
    const int* target = (const int*)d_in[1];
    float* out = (float*)d_out;

    k_zero<<<16, 512>>>();
    k_pass1<<<dim3(GRID1B, BB), THR1>>>(logits, target);
    k_pass2<<<BB, 1024>>>();
    k_pass3<<<dim3(BLK3, BB), THR3>>>();
    k_pass4<<<1, 128>>>(out);
}

// round 7
// speedup vs baseline: 4.6509x; 4.6509x over previous
#include <cuda_runtime.h>
#include <cuda_bf16.h>

// Problem constants (fixed by the dataset)
#define BB      4
#define CC      8
#define NVOX    1048576      // 64*128*128 = 2^20
#define K_RATIO 0.2f

// u16 CE codes: code = 1 + min(floor(ce*2048), 65534); 0 = invalid (ignored voxel)
// coarse bucket = (code-1) >> 4  in [0, 4096)
#define QSCALE  2048.0f
#define NBC     4096
#define NWC     (NBC/2)      // packed u16 pair words for the sampled smem hist

// Exact window around the sampled-threshold estimate
#define WHALF   16
#define WIN     (2*WHALF + 1)    // 33 buckets
#define SUM_SHIFT 43             // packed u64: [63:43]=count, [42:0]=code-1 sum

#define GRID1B  296          // blocks per batch for pass1
#define THR1    256
#define BLK3    74           // blocks per batch for pass3
#define THR3    512

// ---- static device scratch (no allocations allowed) ----
__device__ unsigned short       g_codes[(size_t)BB * NVOX];   // 8 MB
__device__ unsigned int         g_shist[BB][NBC];             // sampled histogram
__device__ unsigned long long   g_win[BB][WIN];               // exact window cnt|sum
__device__ unsigned int         g_acnt[BB];                   // exact count above window
__device__ unsigned long long   g_asum[BB];                   // exact code-sum above window
__device__ unsigned int         g_nvalid[BB];                 // exact valid count
__device__ int                  g_k[BB];
__device__ int                  g_Wlo[BB];

// ---------------------------------------------------------------------------
// Kernel 0: zero accumulators (replayed every graph launch)
// ---------------------------------------------------------------------------
__global__ void k_zero() {
    int tid = blockIdx.x * blockDim.x + threadIdx.x;
    int nthr = gridDim.x * blockDim.x;
    for (int i = tid; i < BB * NBC; i += nthr)
        ((unsigned int*)g_shist)[i] = 0u;
    if (tid < BB * WIN) ((unsigned long long*)g_win)[tid] = 0ull;
    if (tid < BB) { g_acnt[tid] = 0u; g_asum[tid] = 0ull; g_nvalid[tid] = 0u; }
}

// ---------------------------------------------------------------------------
// Pass 1: CE -> u16 codes; sampled (1/4) smem histogram; exact n_valid
// ---------------------------------------------------------------------------
__device__ __forceinline__ unsigned short vox_code(
    float a0, float a1, float a2, float a3,
    float a4, float a5, float a6, float a7, int t) {
    float m = fmaxf(fmaxf(fmaxf(a0, a1), fmaxf(a2, a3)),
                    fmaxf(fmaxf(a4, a5), fmaxf(a6, a7)));
    float s = __expf(a0 - m) + __expf(a1 - m) + __expf(a2 - m) + __expf(a3 - m)
            + __expf(a4 - m) + __expf(a5 - m) + __expf(a6 - m) + __expf(a7 - m);
    float xt = a0;
    if (t == 1) xt = a1;
    if (t == 2) xt = a2;
    if (t == 3) xt = a3;
    if (t == 4) xt = a4;
    if (t == 5) xt = a5;
    if (t == 6) xt = a6;
    if (t == 7) xt = a7;
    float ce = fmaxf(m + __logf(s) - xt, 0.0f);
    if (t == 0) return 0;
    int q = (int)(ce * QSCALE);
    if (q > 65534) q = 65534;
    return (unsigned short)(q + 1);
}

__global__ void __launch_bounds__(THR1, 4)
k_pass1(const float* __restrict__ logits, const int* __restrict__ target) {
    __shared__ unsigned int sh[NWC];      // sampled hist, u16-pair packed
    __shared__ unsigned int vred[THR1 / 32];
    const int tid = threadIdx.x;
    for (int j = tid; j < NWC; j += THR1) sh[j] = 0u;
    __syncthreads();

    const int b = blockIdx.y;
    const float* Lp = logits + (size_t)b * CC * NVOX;
    const int* Tp = target + (size_t)b * NVOX;
    unsigned short* Sp = g_codes + (size_t)b * NVOX;

    const bool sample = ((tid & 3) == 0);
    unsigned int nv = 0;

    const int stride = GRID1B * THR1 * 4;
    for (int i0 = (blockIdx.x * THR1 + tid) * 4; i0 < NVOX; i0 += stride) {
        float4 x0 = *(const float4*)(Lp + 0 * NVOX + i0);
        float4 x1 = *(const float4*)(Lp + 1 * NVOX + i0);
        float4 x2 = *(const float4*)(Lp + 2 * NVOX + i0);
        float4 x3 = *(const float4*)(Lp + 3 * NVOX + i0);
        float4 x4 = *(const float4*)(Lp + 4 * NVOX + i0);
        float4 x5 = *(const float4*)(Lp + 5 * NVOX + i0);
        float4 x6 = *(const float4*)(Lp + 6 * NVOX + i0);
        float4 x7 = *(const float4*)(Lp + 7 * NVOX + i0);
        int4 t4 = *(const int4*)(Tp + i0);

        unsigned short c0 = vox_code(x0.x, x1.x, x2.x, x3.x, x4.x, x5.x, x6.x, x7.x, t4.x);
        unsigned short c1 = vox_code(x0.y, x1.y, x2.y, x3.y, x4.y, x5.y, x6.y, x7.y, t4.y);
        unsigned short c2 = vox_code(x0.z, x1.z, x2.z, x3.z, x4.z, x5.z, x6.z, x7.z, t4.z);
        unsigned short c3 = vox_code(x0.w, x1.w, x2.w, x3.w, x4.w, x5.w, x6.w, x7.w, t4.w);

        nv += (c0 != 0) + (c1 != 0) + (c2 != 0) + (c3 != 0);

        if (sample) {   // 1/4 of lanes feed the threshold-estimation histogram
#define SAMP(C) if (C) { int cw = (int)((C) - 1) >> 4; \
                         atomicAdd(&sh[cw >> 1], (cw & 1) ? 0x10000u : 1u); }
            SAMP(c0) SAMP(c1) SAMP(c2) SAMP(c3)
#undef SAMP
        }

        uint2 st;
        st.x = (unsigned int)c0 | ((unsigned int)c1 << 16);
        st.y = (unsigned int)c2 | ((unsigned int)c3 << 16);
        *(uint2*)(Sp + i0) = st;
    }

    // exact n_valid: integer block reduce + one global atomic
#pragma unroll
    for (int o = 16; o > 0; o >>= 1) nv += __shfl_down_sync(0xFFFFFFFFu, nv, o);
    if ((tid & 31) == 0) vred[tid >> 5] = nv;
    __syncthreads();
    if (tid == 0) {
        unsigned int t = 0;
        for (int j = 0; j < THR1 / 32; j++) t += vred[j];
        atomicAdd(&g_nvalid[b], t);
    }

    // flush sampled histogram (skip empty buckets)
    for (int j = tid; j < NWC; j += THR1) {
        unsigned int w = sh[j];
        unsigned int lo = w & 0xFFFFu;
        unsigned int hi = w >> 16;
        if (lo) atomicAdd(&g_shist[b][2 * j], lo);
        if (hi) atomicAdd(&g_shist[b][2 * j + 1], hi);
    }
}

// ---------------------------------------------------------------------------
// Pass 2: per batch, k (exact from n_valid) and window base from sampled hist
// ---------------------------------------------------------------------------
#define CH (NBC / 1024)   // 4 buckets per thread

__global__ void k_pass2() {
    __shared__ unsigned int part[1024];
    __shared__ unsigned int warpsum[32];
    const int tid = threadIdx.x;
    const int b = blockIdx.x;

    unsigned int s = 0;
    const int base = tid * CH;
#pragma unroll
    for (int j = 0; j < CH; j++) s += g_shist[b][base + j];
    part[tid] = s;
    __syncthreads();

    if (tid < 32) {
        unsigned int w = 0;
#pragma unroll
        for (int j = 0; j < 32; j++) w += part[tid * 32 + j];
        warpsum[tid] = w;
    }
    __syncthreads();

    if (tid == 0) {
        long long stot = 0;
        for (int j = 0; j < 32; j++) stot += warpsum[j];

        int n_valid = (int)g_nvalid[b];
        // replicate reference: trunc(f32(n_valid) * f32(0.2)), clamp [1, n_valid]
        int k = (int)((float)n_valid * K_RATIO);
        if (k < 1) k = 1;
        if (k > n_valid) k = n_valid;   // == 0 iff n_valid == 0
        g_k[b] = k;

        long long ks = k >> 2;          // sampled-space target (1/4 sampling)
        if (ks < 1) ks = 1;
        if (ks > stot) ks = stot;

        int Tt = 0;
        if (stot > 0) {
            long long cum = 0;
            int wsel = 0;
            for (int wi = 31; wi >= 0; wi--) {
                if (cum + (long long)warpsum[wi] >= ks) { wsel = wi; break; }
                cum += warpsum[wi];
            }
            int psel = wsel * 32;
            for (int pi = wsel * 32 + 31; pi >= wsel * 32; pi--) {
                if (cum + (long long)part[pi] >= ks) { psel = pi; break; }
                cum += part[pi];
            }
            Tt = psel * CH;
            for (int j = psel * CH + CH - 1; j >= psel * CH; j--) {
                unsigned int c = g_shist[b][j];
                if (cum + (long long)c >= ks) { Tt = j; break; }
                cum += c;
            }
        }
        int Wlo = Tt - WHALF;
        if (Wlo < 0) Wlo = 0;
        if (Wlo > NBC - WIN) Wlo = NBC - WIN;
        g_Wlo[b] = Wlo;
    }
}

// ---------------------------------------------------------------------------
// Pass 3: exact window histogram (count+sum) and exact above-window aggregates
// ---------------------------------------------------------------------------
__global__ void __launch_bounds__(THR3)
k_pass3() {
    __shared__ unsigned long long win[WIN];
    __shared__ unsigned long long r1[THR3 / 32], r2[THR3 / 32];
    const int b = blockIdx.y;
    const int Wlo = g_Wlo[b];
    const int tid = threadIdx.x;
    if (tid < WIN) win[tid] = 0ull;
    __syncthreads();

    const unsigned short* Sp = g_codes + (size_t)b * NVOX;

    unsigned int acnt = 0;
    unsigned int asum = 0;   // per-thread sum of (code-1) above window; max ~1.8e6 < 2^32

    const int stride = BLK3 * THR3 * 16;
    for (int i0 = (blockIdx.x * THR3 + tid) * 16; i0 < NVOX; i0 += stride) {
        uint4 wa = *(const uint4*)(Sp + i0);
        uint4 wb = *(const uint4*)(Sp + i0 + 8);
#define PROC(W) { \
        unsigned int c = (W) & 0xFFFFu; \
        if (c) { unsigned int v = c - 1u; int rel = (int)(v >> 4) - Wlo; \
            if (rel >= WIN) { acnt++; asum += v; } \
            else if (rel >= 0) atomicAdd(&win[rel], (1ull << SUM_SHIFT) + (unsigned long long)v); } \
        c = (W) >> 16; \
        if (c) { unsigned int v = c - 1u; int rel = (int)(v >> 4) - Wlo; \
            if (rel >= WIN) { acnt++; asum += v; } \
            else if (rel >= 0) atomicAdd(&win[rel], (1ull << SUM_SHIFT) + (unsigned long long)v); } }
        PROC(wa.x) PROC(wa.y) PROC(wa.z) PROC(wa.w)
        PROC(wb.x) PROC(wb.y) PROC(wb.z) PROC(wb.w)
#undef PROC
    }

    // integer block reduce of above-window aggregates (deterministic)
    unsigned long long la = acnt, ls = asum;
#pragma unroll
    for (int o = 16; o > 0; o >>= 1) {
        la += __shfl_down_sync(0xFFFFFFFFu, la, o);
        ls += __shfl_down_sync(0xFFFFFFFFu, ls, o);
    }
    const int wid = tid >> 5, lane = tid & 31;
    if (lane == 0) { r1[wid] = la; r2[wid] = ls; }
    __syncthreads();
    if (tid == 0) {
        unsigned long long ta = 0, ts = 0;
        for (int j = 0; j < THR3 / 32; j++) { ta += r1[j]; ts += r2[j]; }
        atomicAdd(&g_acnt[b], (unsigned int)ta);
        atomicAdd(&g_asum[b], ts);
    }
    if (tid < WIN) {
        unsigned long long w = win[tid];
        if (w) atomicAdd(&g_win[b][tid], w);
    }
}

// ---------------------------------------------------------------------------
// Pass 4: exact selection within window, combine, final mean
// ---------------------------------------------------------------------------
__global__ void k_pass4(float* __restrict__ out) {
    __shared__ double per[BB];
    const int tid = threadIdx.x;
    if (tid < BB) {
        const int b = tid;
        const int nv = (int)g_nvalid[b];
        const long long k = g_k[b];
        double p = 0.0;
        if (nv > 0) {
            unsigned long long cnt[WIN], sum[WIN];
            for (int j = 0; j < WIN; j++) {
                unsigned long long w = g_win[b][j];
                cnt[j] = w >> SUM_SHIFT;
                sum[j] = w & ((1ull << SUM_SHIFT) - 1ull);
            }
            long long cum = (long long)g_acnt[b];
            double fsum = (double)g_asum[b];
            double top;
            if (cum >= k) {
                // window badly placed (shouldn't happen): mean approximation
                top = fsum * ((double)k / (double)cum);
            } else {
                int j = WIN - 1;
                while (j >= 0 && cum + (long long)cnt[j] < k) {
                    cum += (long long)cnt[j];
                    fsum += (double)sum[j];
                    j--;
                }
                if (j < 0) {
                    top = fsum;   // window exhausted (shouldn't happen)
                } else {
                    long long r = k - cum;   // 1..cnt[j]
                    top = fsum + (double)r * ((double)sum[j] / (double)cnt[j]);
                }
            }
            // +0.5 LSB de-bias for the floor quantization, then dequantize
            p = (top + 0.5 * (double)k) / (double)QSCALE / (double)k;
        }
        per[b] = p;
    }
    __syncthreads();
    if (tid == 0) {
        double acc = 0.0;
        for (int b = 0; b < BB; b++) acc += per[b];
        out[0] = (float)(acc / (double)BB);
    }
}

// ---------------------------------------------------------------------------
// Launch
// ---------------------------------------------------------------------------
extern "C" void kernel_launch(void* const* d_in, const int* in_sizes, int n_in,
                              void* d_out, int out_size) {
    const float* logits = (const float*)d_in[0];
    const int* target = (const int*)d_in[1];
    float* out = (float*)d_out;

    k_zero<<<8, 512>>>();
    k_pass1<<<dim3(GRID1B, BB), THR1>>>(logits, target);
    k_pass2<<<BB, 1024>>>();
    k_pass3<<<dim3(BLK3, BB), THR3>>>();
    k_pass4<<<1, 128>>>(out);
}